// round 11
// baseline (speedup 1.0000x reference)
#include <cuda_runtime.h>
#include <math.h>

#define NN     8192
#define TILE   64
#define NBLK   (NN / TILE)                 // 128
#define NPAIRS (NBLK * (NBLK + 1) / 2)     // 8256

// Deterministic partial rowsums: g_partial[slot][row], each (row,slot) written
// exactly once per launch (no atomics -> bit-identical every call).
__device__ float g_partial[(size_t)NBLK * NN];   // 4 MB scratch
__device__ float g_rinv[NN];

// Map linear pair index p -> (bi, bj) with bi <= bj.
// offset(bi) = bi*(2*NBLK+1-bi)/2
__device__ __forceinline__ void decode_pair(int p, int& bi, int& bj) {
    const int C = 2 * NBLK + 1;                       // 257
    float disc = (float)(C * C - 8 * p);
    int x = (int)(((float)C - sqrtf(disc)) * 0.5f);
    if (x < 0) x = 0;
    while (x > 0 && x * (C - x) / 2 > p) x--;
    while ((x + 1) * (C - (x + 1)) / 2 <= p) x++;
    bi = x;
    bj = bi + (p - bi * (C - bi) / 2);
}

// ---------------------------------------------------------------------------
// Pass 1: per-tile-pair rowsums of s = relu((A + A^T)/2).
// For pair (bi,bj): row sums of the tile go to slot bj (rows of block bi);
// by symmetry the column sums are the row sums of block bj's rows -> slot bi.
// ---------------------------------------------------------------------------
__global__ __launch_bounds__(256) void rowsum_kernel(const float* __restrict__ A) {
    __shared__ float trs[TILE][TILE + 1];   // A[bj-tile][bi-tile], transposed
    __shared__ float rowpart[2][TILE];
    __shared__ float colbuf[4][TILE];

    int bi, bj;
    decode_pair(blockIdx.x, bi, bj);
    const int tx = threadIdx.x;   // 0..63 (column within tile)
    const int ty = threadIdx.y;   // 0..3
    const int gi0 = bi * TILE, gj0 = bj * TILE;

    // Load lower tile A[gj0+r][gi0+c] transposed into smem (coalesced loads,
    // stride-65 stores -> conflict-free).
    #pragma unroll
    for (int k = 0; k < 16; k++) {
        int r = ty * 16 + k;
        trs[tx][r] = A[(size_t)(gj0 + r) * NN + (gi0 + tx)];
    }
    __syncthreads();

    float csum = 0.0f;  // column sum for column tx (this thread's 16 rows)
    #pragma unroll
    for (int k = 0; k < 16; k++) {
        int i = ty * 16 + k;
        float a = A[(size_t)(gi0 + i) * NN + (gj0 + tx)];     // A[gi][gj]
        float b = trs[i][tx];                                 // A[gj][gi]
        float s = fmaxf(0.5f * (a + b), 0.0f);
        csum += s;
        // Row reduction across the 32 lanes of this warp (fixed i per warp).
        float rs = s;
        rs += __shfl_down_sync(0xffffffffu, rs, 16);
        rs += __shfl_down_sync(0xffffffffu, rs, 8);
        rs += __shfl_down_sync(0xffffffffu, rs, 4);
        rs += __shfl_down_sync(0xffffffffu, rs, 2);
        rs += __shfl_down_sync(0xffffffffu, rs, 1);
        if ((tx & 31) == 0) rowpart[tx >> 5][i] = rs;
    }
    colbuf[ty][tx] = csum;
    __syncthreads();

    if (ty == 0) {
        // row sums for rows gi0..gi0+63 -> slot bj (coalesced store)
        g_partial[(size_t)bj * NN + gi0 + tx] = rowpart[0][tx] + rowpart[1][tx];
    } else if (ty == 1 && bi != bj) {
        // column sums == row sums for rows gj0..gj0+63 -> slot bi
        g_partial[(size_t)bi * NN + gj0 + tx] =
            colbuf[0][tx] + colbuf[1][tx] + colbuf[2][tx] + colbuf[3][tx];
    }
}

// ---------------------------------------------------------------------------
// Pass 2: rowsum = 1 (self-loop) + sum of 128 partials; r_inv = rsqrt(rowsum).
// rowsum >= 1 always, so no inf handling needed.
// ---------------------------------------------------------------------------
__global__ void rinv_kernel() {
    int i = blockIdx.x * blockDim.x + threadIdx.x;
    float acc = 1.0f;
    #pragma unroll 8
    for (int s = 0; s < NBLK; s++)
        acc += g_partial[(size_t)s * NN + i];   // coalesced across threads
    g_rinv[i] = rsqrtf(acc);
}

// ---------------------------------------------------------------------------
// Pass 3: out[i][j] = r_inv[i] * (s + (i==j)) * r_inv[j], upper tile written
// directly, mirrored tile written via smem transpose (both fully coalesced).
// ---------------------------------------------------------------------------
__global__ __launch_bounds__(256) void scale_kernel(const float* __restrict__ A,
                                                    float* __restrict__ out) {
    __shared__ float trs[TILE][TILE + 1];
    __shared__ float sot[TILE][TILE + 1];
    __shared__ float rinv_i[TILE];
    __shared__ float rinv_j[TILE];

    int bi, bj;
    decode_pair(blockIdx.x, bi, bj);
    const int tx = threadIdx.x;
    const int ty = threadIdx.y;
    const int gi0 = bi * TILE, gj0 = bj * TILE;

    if (ty == 0) rinv_i[tx] = g_rinv[gi0 + tx];
    if (ty == 1) rinv_j[tx] = g_rinv[gj0 + tx];

    #pragma unroll
    for (int k = 0; k < 16; k++) {
        int r = ty * 16 + k;
        trs[tx][r] = A[(size_t)(gj0 + r) * NN + (gi0 + tx)];
    }
    __syncthreads();

    const float rj = rinv_j[tx];
    #pragma unroll
    for (int k = 0; k < 16; k++) {
        int i = ty * 16 + k;
        float a = A[(size_t)(gi0 + i) * NN + (gj0 + tx)];
        float s = fmaxf(0.5f * (a + trs[i][tx]), 0.0f);
        if (gi0 + i == gj0 + tx) s += 1.0f;        // self-loop on the diagonal
        float v = rinv_i[i] * s * rj;
        out[(size_t)(gi0 + i) * NN + (gj0 + tx)] = v;
        sot[i][tx] = v;
    }

    if (bi != bj) {
        __syncthreads();
        #pragma unroll
        for (int k = 0; k < 16; k++) {
            int r = ty * 16 + k;
            out[(size_t)(gj0 + r) * NN + (gi0 + tx)] = sot[tx][r];
        }
    }
}

extern "C" void kernel_launch(void* const* d_in, const int* in_sizes, int n_in,
                              void* d_out, int out_size) {
    const float* A = (const float*)d_in[0];
    float* out = (float*)d_out;

    dim3 blk(64, 4);
    rowsum_kernel<<<NPAIRS, blk>>>(A);
    rinv_kernel<<<NN / 256, 256>>>();
    scale_kernel<<<NPAIRS, blk>>>(A, out);
}

// round 12
// speedup vs baseline: 1.0013x; 1.0013x over previous
#include <cuda_runtime.h>
#include <math.h>

#define NN     8192
#define TILE   64
#define NBLK   (NN / TILE)                 // 128
#define NPAIRS (NBLK * (NBLK + 1) / 2)     // 8256

// Deterministic partial rowsums: g_partial[slot][row], each (row,slot) written
// exactly once per launch (no atomics -> bit-identical every call).
__device__ float g_partial[(size_t)NBLK * NN];   // 4 MB scratch
__device__ float g_rinv[NN];

// Map linear pair index p -> (bi, bj) with bi <= bj.
// offset(bi) = bi*(2*NBLK+1-bi)/2
__device__ __forceinline__ void decode_pair(int p, int& bi, int& bj) {
    const int C = 2 * NBLK + 1;                       // 257
    float disc = (float)(C * C - 8 * p);
    int x = (int)(((float)C - sqrtf(disc)) * 0.5f);
    if (x < 0) x = 0;
    while (x > 0 && x * (C - x) / 2 > p) x--;
    while ((x + 1) * (C - (x + 1)) / 2 <= p) x++;
    bi = x;
    bj = bi + (p - bi * (C - bi) / 2);
}

// ---------------------------------------------------------------------------
// Pass 1: per-tile-pair rowsums of s = relu((A + A^T)/2).
// For pair (bi,bj): row sums of the tile go to slot bj (rows of block bi);
// by symmetry the column sums are the row sums of block bj's rows -> slot bi.
// ---------------------------------------------------------------------------
__global__ __launch_bounds__(256) void rowsum_kernel(const float* __restrict__ A) {
    __shared__ float trs[TILE][TILE + 1];   // A[bj-tile][bi-tile], transposed
    __shared__ float rowpart[2][TILE];
    __shared__ float colbuf[4][TILE];

    int bi, bj;
    decode_pair(blockIdx.x, bi, bj);
    const int tx = threadIdx.x;   // 0..63 (column within tile)
    const int ty = threadIdx.y;   // 0..3
    const int gi0 = bi * TILE, gj0 = bj * TILE;

    // Load lower tile A[gj0+r][gi0+c] transposed into smem (coalesced loads,
    // stride-65 stores -> conflict-free).
    #pragma unroll
    for (int k = 0; k < 16; k++) {
        int r = ty * 16 + k;
        trs[tx][r] = A[(size_t)(gj0 + r) * NN + (gi0 + tx)];
    }
    __syncthreads();

    float csum = 0.0f;  // column sum for column tx (this thread's 16 rows)
    #pragma unroll
    for (int k = 0; k < 16; k++) {
        int i = ty * 16 + k;
        float a = A[(size_t)(gi0 + i) * NN + (gj0 + tx)];     // A[gi][gj]
        float b = trs[i][tx];                                 // A[gj][gi]
        float s = fmaxf(0.5f * (a + b), 0.0f);
        csum += s;
        // Row reduction across the 32 lanes of this warp (fixed i per warp).
        float rs = s;
        rs += __shfl_down_sync(0xffffffffu, rs, 16);
        rs += __shfl_down_sync(0xffffffffu, rs, 8);
        rs += __shfl_down_sync(0xffffffffu, rs, 4);
        rs += __shfl_down_sync(0xffffffffu, rs, 2);
        rs += __shfl_down_sync(0xffffffffu, rs, 1);
        if ((tx & 31) == 0) rowpart[tx >> 5][i] = rs;
    }
    colbuf[ty][tx] = csum;
    __syncthreads();

    if (ty == 0) {
        // row sums for rows gi0..gi0+63 -> slot bj (coalesced store)
        g_partial[(size_t)bj * NN + gi0 + tx] = rowpart[0][tx] + rowpart[1][tx];
    } else if (ty == 1 && bi != bj) {
        // column sums == row sums for rows gj0..gj0+63 -> slot bi
        g_partial[(size_t)bi * NN + gj0 + tx] =
            colbuf[0][tx] + colbuf[1][tx] + colbuf[2][tx] + colbuf[3][tx];
    }
}

// ---------------------------------------------------------------------------
// Pass 2: rowsum = 1 (self-loop) + sum of 128 partials; r_inv = rsqrt(rowsum).
// rowsum >= 1 always, so no inf handling needed.
// ---------------------------------------------------------------------------
__global__ void rinv_kernel() {
    int i = blockIdx.x * blockDim.x + threadIdx.x;
    float acc = 1.0f;
    #pragma unroll 8
    for (int s = 0; s < NBLK; s++)
        acc += g_partial[(size_t)s * NN + i];   // coalesced across threads
    g_rinv[i] = rsqrtf(acc);
}

// ---------------------------------------------------------------------------
// Pass 3: out[i][j] = r_inv[i] * (s + (i==j)) * r_inv[j], upper tile written
// directly, mirrored tile written via smem transpose (both fully coalesced).
// ---------------------------------------------------------------------------
__global__ __launch_bounds__(256) void scale_kernel(const float* __restrict__ A,
                                                    float* __restrict__ out) {
    __shared__ float trs[TILE][TILE + 1];
    __shared__ float sot[TILE][TILE + 1];
    __shared__ float rinv_i[TILE];
    __shared__ float rinv_j[TILE];

    int bi, bj;
    decode_pair(blockIdx.x, bi, bj);
    const int tx = threadIdx.x;
    const int ty = threadIdx.y;
    const int gi0 = bi * TILE, gj0 = bj * TILE;

    if (ty == 0) rinv_i[tx] = g_rinv[gi0 + tx];
    if (ty == 1) rinv_j[tx] = g_rinv[gj0 + tx];

    #pragma unroll
    for (int k = 0; k < 16; k++) {
        int r = ty * 16 + k;
        trs[tx][r] = A[(size_t)(gj0 + r) * NN + (gi0 + tx)];
    }
    __syncthreads();

    const float rj = rinv_j[tx];
    #pragma unroll
    for (int k = 0; k < 16; k++) {
        int i = ty * 16 + k;
        float a = A[(size_t)(gi0 + i) * NN + (gj0 + tx)];
        float s = fmaxf(0.5f * (a + trs[i][tx]), 0.0f);
        if (gi0 + i == gj0 + tx) s += 1.0f;        // self-loop on the diagonal
        float v = rinv_i[i] * s * rj;
        out[(size_t)(gi0 + i) * NN + (gj0 + tx)] = v;
        sot[i][tx] = v;
    }

    if (bi != bj) {
        __syncthreads();
        #pragma unroll
        for (int k = 0; k < 16; k++) {
            int r = ty * 16 + k;
            out[(size_t)(gj0 + r) * NN + (gi0 + tx)] = sot[tx][r];
        }
    }
}

extern "C" void kernel_launch(void* const* d_in, const int* in_sizes, int n_in,
                              void* d_out, int out_size) {
    const float* A = (const float*)d_in[0];
    float* out = (float*)d_out;

    dim3 blk(64, 4);
    rowsum_kernel<<<NPAIRS, blk>>>(A);
    rinv_kernel<<<NN / 256, 256>>>();
    scale_kernel<<<NPAIRS, blk>>>(A, out);
}